// round 4
// baseline (speedup 1.0000x reference)
#include <cuda_runtime.h>

// y = FWHT(G * Perm(FWHT(x * B))), orthonormal, L = 16384, fused one-pass.
//
// Radix-32, 512 threads/CTA, one row/CTA, 2 CTAs/SM. 3 register phases/FWHT:
//   P1: regs = n bits {0,1,11,12,13}, lanes = bits 2..6  -> global IO coalesced
//   P2: regs = n bits {2,3,8,9,10},   lanes = bits {0,1,4,5,6} (scalar smem)
//   P3: regs = n bits {4,5,6,7}+bit0, lanes = bits {1,2,3,12,8} (float2 smem)
// XOR swizzle w(n) = n ^ ((((n>>5)^(n>>10))&7)<<2): bijective, float4/float2-
// preserving, all phase layouts bank-conflict-free, zero padding (64KB smem).
//
// Permutation handling (prep kernel, every launch):
//   Gp[Pi[n]] = G[n] / 16384   (G + final scale folded to the store side)
//   Pisw[n]   = sw(Pi[n])      (precomputed swizzled gather addresses)
// Main kernel: pass5 stores z = y1 * Gp (regular float2), prefetches all 32
// Pisw into regs BEFORE the barrier, then the gather is pure LDS.

#define L_N        16384
#define NT         512
#define SMEM_BYTES (L_N * 4)   // 65536

__device__ int   g_Pisw[L_N];
__device__ float g_Gp[L_N];

__device__ __forceinline__ int sw(int n) {
    return n ^ (((((unsigned)n >> 5) ^ ((unsigned)n >> 10)) & 7u) << 2);
}

__device__ __forceinline__ void bfly(float &a, float &b) {
    float t0 = a + b;
    float t1 = a - b;
    a = t0; b = t1;
}

__device__ __forceinline__ void fwht32(float r[32]) {
#pragma unroll
    for (int m = 1; m < 32; m <<= 1) {
#pragma unroll
        for (int i = 0; i < 32; i++) {
            if ((i & m) == 0) bfly(r[i], r[i | m]);
        }
    }
}

// 4-bit FWHT over high reg index (r[2*ih + jl], jl is a passenger bit)
__device__ __forceinline__ void fwht16x2(float r[32]) {
#pragma unroll
    for (int m = 1; m < 16; m <<= 1) {
#pragma unroll
        for (int ih = 0; ih < 16; ih++) {
            if ((ih & m) == 0) {
                bfly(r[2 * ih],     r[2 * (ih | m)]);
                bfly(r[2 * ih + 1], r[2 * (ih | m) + 1]);
            }
        }
    }
}

__global__ void prep_kernel(const float* __restrict__ Gv,
                            const int* __restrict__ Pi) {
    int n = blockIdx.x * blockDim.x + threadIdx.x;
    if (n < L_N) {
        int p = Pi[n];
        g_Pisw[n] = sw(p);
        g_Gp[p]   = Gv[n] * (1.0f / 16384.0f);
    }
}

__global__ __launch_bounds__(NT, 2)
void fwht_fused_kernel(const float* __restrict__ x,
                       const float* __restrict__ Bv,
                       float* __restrict__ out) {
    extern __shared__ float s[];
    const int t = threadIdx.x;
    const size_t row = blockIdx.x;

    float r[32];

    // thread->n base for P2: l0,l1 -> n0,n1 ; l2..l4 -> n4..n6 ; t5->n7, t6..t8->n11..13
    const int p2base = (t & 3)
                     | (((t >> 2) & 7) << 4)
                     | (((t >> 5) & 1) << 7)
                     | ((t >> 6) << 11);
    // thread->n base for P3: l0..l2 -> n1..n3, l3->n12, l4->n8 ; t5..t8 -> n9,n10,n11,n13
    const int p3base = ((t & 7) << 1)
                     | (((t >> 3) & 1) << 12)
                     | (((t >> 4) & 1) << 8)
                     | (((t >> 5) & 1) << 9)
                     | (((t >> 6) & 1) << 10)
                     | (((t >> 7) & 1) << 11)
                     | ((t >> 8) << 13);

    // ===== FWHT #1, P1: bits {0,1,11,12,13}, coalesced global load =====
    {
        const float4* __restrict__ x4 = reinterpret_cast<const float4*>(x + row * L_N);
        const float4* __restrict__ B4 = reinterpret_cast<const float4*>(Bv);
#pragma unroll
        for (int k = 0; k < 8; k++) {
            float4 xv = x4[(k << 9) + t];
            float4 bv = B4[(k << 9) + t];
            r[4 * k + 0] = xv.x * bv.x;
            r[4 * k + 1] = xv.y * bv.y;
            r[4 * k + 2] = xv.z * bv.z;
            r[4 * k + 3] = xv.w * bv.w;
        }
    }
    fwht32(r);
#pragma unroll
    for (int k = 0; k < 8; k++) {
        int n = (k << 11) | (t << 2);
        *reinterpret_cast<float4*>(&s[sw(n)]) =
            make_float4(r[4 * k], r[4 * k + 1], r[4 * k + 2], r[4 * k + 3]);
    }
    __syncthreads();

    // ===== FWHT #1, P2: bits {2,3,8,9,10} =====
#pragma unroll
    for (int q = 0; q < 32; q++) {
        int n = p2base | ((q & 3) << 2) | ((q >> 2) << 8);
        r[q] = s[sw(n)];
    }
    fwht32(r);
#pragma unroll
    for (int q = 0; q < 32; q++) {
        int n = p2base | ((q & 3) << 2) | ((q >> 2) << 8);
        s[sw(n)] = r[q];
    }
    __syncthreads();

    // ===== FWHT #1, P3: bits {4,5,6,7} (bit 0 passenger) =====
#pragma unroll
    for (int ih = 0; ih < 16; ih++) {
        float2 v = *reinterpret_cast<const float2*>(&s[sw(p3base | (ih << 4))]);
        r[2 * ih] = v.x; r[2 * ih + 1] = v.y;
    }
    fwht16x2(r);

    // ===== pass 5: z = y1 * Gp (fused G+scale), store; prefetch Pisw =====
#pragma unroll
    for (int ih = 0; ih < 16; ih++) {
        int m = p3base | (ih << 4);
        float2 gp = *reinterpret_cast<const float2*>(&g_Gp[m]);
        *reinterpret_cast<float2*>(&s[sw(m)]) =
            make_float2(r[2 * ih] * gp.x, r[2 * ih + 1] * gp.y);
    }
    int pv[32];
#pragma unroll
    for (int ih = 0; ih < 16; ih++) {
        int2 p = *reinterpret_cast<const int2*>(&g_Pisw[p3base | (ih << 4)]);
        pv[2 * ih] = p.x; pv[2 * ih + 1] = p.y;
    }
    __syncthreads();

    // ===== gather: pure LDS, addresses pre-swizzled =====
#pragma unroll
    for (int i = 0; i < 32; i++) r[i] = s[pv[i]];
    __syncthreads();   // all gathers complete before smem is overwritten

    // ===== FWHT #2, P3: bits {4,5,6,7} =====
    fwht16x2(r);
#pragma unroll
    for (int ih = 0; ih < 16; ih++) {
        *reinterpret_cast<float2*>(&s[sw(p3base | (ih << 4))]) =
            make_float2(r[2 * ih], r[2 * ih + 1]);
    }
    __syncthreads();

    // ===== FWHT #2, P2: bits {2,3,8,9,10} =====
#pragma unroll
    for (int q = 0; q < 32; q++) {
        int n = p2base | ((q & 3) << 2) | ((q >> 2) << 8);
        r[q] = s[sw(n)];
    }
    fwht32(r);
#pragma unroll
    for (int q = 0; q < 32; q++) {
        int n = p2base | ((q & 3) << 2) | ((q >> 2) << 8);
        s[sw(n)] = r[q];
    }
    __syncthreads();

    // ===== FWHT #2, P1: bits {0,1,11,12,13}, coalesced store (scale pre-folded) =====
#pragma unroll
    for (int k = 0; k < 8; k++) {
        int n = (k << 11) | (t << 2);
        float4 v = *reinterpret_cast<const float4*>(&s[sw(n)]);
        r[4 * k + 0] = v.x; r[4 * k + 1] = v.y;
        r[4 * k + 2] = v.z; r[4 * k + 3] = v.w;
    }
    fwht32(r);
    {
        float4* __restrict__ o4 = reinterpret_cast<float4*>(out + row * L_N);
#pragma unroll
        for (int k = 0; k < 8; k++) {
            o4[(k << 9) + t] = make_float4(r[4 * k], r[4 * k + 1],
                                           r[4 * k + 2], r[4 * k + 3]);
        }
    }
}

extern "C" void kernel_launch(void* const* d_in, const int* in_sizes, int n_in,
                              void* d_out, int out_size) {
    const float* x  = (const float*)d_in[0];
    const float* B  = (const float*)d_in[1];
    const float* G  = (const float*)d_in[2];
    const int*   Pi = (const int*)d_in[3];
    float* out = (float*)d_out;

    int rows = in_sizes[0] / L_N;

    cudaFuncSetAttribute(fwht_fused_kernel,
                         cudaFuncAttributeMaxDynamicSharedMemorySize, SMEM_BYTES);

    prep_kernel<<<L_N / NT, NT>>>(G, Pi);
    fwht_fused_kernel<<<rows, NT, SMEM_BYTES>>>(x, B, out);
}

// round 5
// speedup vs baseline: 1.0973x; 1.0973x over previous
#include <cuda_runtime.h>

// y = FWHT(G * Perm(FWHT(x * B))), orthonormal, L = 16384, fused one-pass.
//
// Radix-32, 512 threads/CTA, one row/CTA, 2 CTAs/SM. 3 register phases/FWHT:
//   P1: regs = n bits {0,1,11,12,13}, lanes = bits 2..6  -> global IO coalesced
//   P2: regs = n bits {2,3,8,9,10},   lanes = bits {0,1,4,5,6} (scalar smem)
//   P3: regs = n bits {4,5,6,7}+bit0, lanes = bits {1,2,3,12,8} (float2 smem)
// XOR swizzle w(n) = n ^ ((((n>>5)^(n>>10))&7)<<2): bijective, float4/float2-
// preserving, all phase layouts bank-conflict-free, zero padding (64KB smem).
//
// Prep kernel (every launch, trivial):
//   Bbits[w]  = sign bits of B[32w..32w+31]   (2KB; +-1 mul -> exact sign XOR)
//   Pisw[n]   = sw(Pi[n]) as u16              (32KB; pure-LDS gather, no ALU)
//   Gp[Pi[n]] = G[n] / 16384                  (G + final scale folded to the
//                                              pass-5 store side)

#define L_N        16384
#define NT         512
#define SMEM_BYTES (L_N * 4)   // 65536

__device__ unsigned       g_Bbits[L_N / 32];
__device__ unsigned short g_Pisw[L_N];
__device__ float          g_Gp[L_N];

__device__ __forceinline__ int sw(int n) {
    return n ^ (((((unsigned)n >> 5) ^ ((unsigned)n >> 10)) & 7u) << 2);
}

__device__ __forceinline__ void bfly(float &a, float &b) {
    float t0 = a + b;
    float t1 = a - b;
    a = t0; b = t1;
}

__device__ __forceinline__ void fwht32(float r[32]) {
#pragma unroll
    for (int m = 1; m < 32; m <<= 1) {
#pragma unroll
        for (int i = 0; i < 32; i++) {
            if ((i & m) == 0) bfly(r[i], r[i | m]);
        }
    }
}

// 4-bit FWHT over high reg index (r[2*ih + jl], jl is a passenger bit)
__device__ __forceinline__ void fwht16x2(float r[32]) {
#pragma unroll
    for (int m = 1; m < 16; m <<= 1) {
#pragma unroll
        for (int ih = 0; ih < 16; ih++) {
            if ((ih & m) == 0) {
                bfly(r[2 * ih],     r[2 * (ih | m)]);
                bfly(r[2 * ih + 1], r[2 * (ih | m) + 1]);
            }
        }
    }
}

__global__ void prep_kernel(const float* __restrict__ Gv,
                            const int* __restrict__ Pi,
                            const float* __restrict__ Bv) {
    int n = blockIdx.x * blockDim.x + threadIdx.x;   // 16384 threads
    int p = Pi[n];
    g_Pisw[n] = (unsigned short)sw(p);
    g_Gp[p]   = Gv[n] * (1.0f / 16384.0f);
    unsigned sb  = __float_as_uint(Bv[n]) >> 31;
    unsigned bal = __ballot_sync(0xffffffffu, sb);
    if ((n & 31) == 0) g_Bbits[n >> 5] = bal;
}

__global__ __launch_bounds__(NT, 2)
void fwht_fused_kernel(const float* __restrict__ x,
                       float* __restrict__ out) {
    extern __shared__ float s[];
    const int t = threadIdx.x;
    const size_t row = blockIdx.x;

    float r[32];

    // thread->n base for P2: l0,l1 -> n0,n1 ; l2..l4 -> n4..n6 ; t5->n7, t6..t8->n11..13
    const int p2base = (t & 3)
                     | (((t >> 2) & 7) << 4)
                     | (((t >> 5) & 1) << 7)
                     | ((t >> 6) << 11);
    // thread->n base for P3: l0..l2 -> n1..n3, l3->n12, l4->n8 ; t5..t8 -> n9,n10,n11,n13
    const int p3base = ((t & 7) << 1)
                     | (((t >> 3) & 1) << 12)
                     | (((t >> 4) & 1) << 8)
                     | (((t >> 5) & 1) << 9)
                     | (((t >> 6) & 1) << 10)
                     | (((t >> 7) & 1) << 11)
                     | ((t >> 8) << 13);

    // ===== FWHT #1, P1: bits {0,1,11,12,13}, coalesced global load, B via sign XOR =====
    {
        const float4* __restrict__ x4 = reinterpret_cast<const float4*>(x + row * L_N);
#pragma unroll
        for (int k = 0; k < 8; k++) {
            float4 xv = x4[(k << 9) + t];
            unsigned u = g_Bbits[(k << 6) + (t >> 3)] >> ((t & 7) << 2);
            r[4 * k + 0] = __uint_as_float(__float_as_uint(xv.x) ^ ((u & 1u) << 31));
            r[4 * k + 1] = __uint_as_float(__float_as_uint(xv.y) ^ ((u & 2u) << 30));
            r[4 * k + 2] = __uint_as_float(__float_as_uint(xv.z) ^ ((u & 4u) << 29));
            r[4 * k + 3] = __uint_as_float(__float_as_uint(xv.w) ^ ((u & 8u) << 28));
        }
    }
    fwht32(r);
#pragma unroll
    for (int k = 0; k < 8; k++) {
        int n = (k << 11) | (t << 2);
        *reinterpret_cast<float4*>(&s[sw(n)]) =
            make_float4(r[4 * k], r[4 * k + 1], r[4 * k + 2], r[4 * k + 3]);
    }
    __syncthreads();

    // ===== FWHT #1, P2: bits {2,3,8,9,10} =====
#pragma unroll
    for (int q = 0; q < 32; q++) {
        int n = p2base | ((q & 3) << 2) | ((q >> 2) << 8);
        r[q] = s[sw(n)];
    }
    fwht32(r);
#pragma unroll
    for (int q = 0; q < 32; q++) {
        int n = p2base | ((q & 3) << 2) | ((q >> 2) << 8);
        s[sw(n)] = r[q];
    }
    __syncthreads();

    // ===== FWHT #1, P3: bits {4,5,6,7} (bit 0 passenger) =====
#pragma unroll
    for (int ih = 0; ih < 16; ih++) {
        float2 v = *reinterpret_cast<const float2*>(&s[sw(p3base | (ih << 4))]);
        r[2 * ih] = v.x; r[2 * ih + 1] = v.y;
    }
    fwht16x2(r);

    // ===== pass 5: z = y1 * Gp (G + scale folded), float2 store =====
#pragma unroll
    for (int ih = 0; ih < 16; ih++) {
        int m = p3base | (ih << 4);
        float2 gp = *reinterpret_cast<const float2*>(&g_Gp[m]);
        *reinterpret_cast<float2*>(&s[sw(m)]) =
            make_float2(r[2 * ih] * gp.x, r[2 * ih + 1] * gp.y);
    }
    __syncthreads();

    // ===== gather: pure LDS, u16 pre-swizzled addresses =====
#pragma unroll
    for (int ih = 0; ih < 16; ih++) {
        int n = p3base | (ih << 4);
        ushort2 p = *reinterpret_cast<const ushort2*>(&g_Pisw[n]);
        r[2 * ih]     = s[p.x];
        r[2 * ih + 1] = s[p.y];
    }
    __syncthreads();   // all gathers complete before smem is overwritten

    // ===== FWHT #2, P3: bits {4,5,6,7} =====
    fwht16x2(r);
#pragma unroll
    for (int ih = 0; ih < 16; ih++) {
        *reinterpret_cast<float2*>(&s[sw(p3base | (ih << 4))]) =
            make_float2(r[2 * ih], r[2 * ih + 1]);
    }
    __syncthreads();

    // ===== FWHT #2, P2: bits {2,3,8,9,10} =====
#pragma unroll
    for (int q = 0; q < 32; q++) {
        int n = p2base | ((q & 3) << 2) | ((q >> 2) << 8);
        r[q] = s[sw(n)];
    }
    fwht32(r);
#pragma unroll
    for (int q = 0; q < 32; q++) {
        int n = p2base | ((q & 3) << 2) | ((q >> 2) << 8);
        s[sw(n)] = r[q];
    }
    __syncthreads();

    // ===== FWHT #2, P1: bits {0,1,11,12,13}, coalesced store (scale pre-folded) =====
#pragma unroll
    for (int k = 0; k < 8; k++) {
        int n = (k << 11) | (t << 2);
        float4 v = *reinterpret_cast<const float4*>(&s[sw(n)]);
        r[4 * k + 0] = v.x; r[4 * k + 1] = v.y;
        r[4 * k + 2] = v.z; r[4 * k + 3] = v.w;
    }
    fwht32(r);
    {
        float4* __restrict__ o4 = reinterpret_cast<float4*>(out + row * L_N);
#pragma unroll
        for (int k = 0; k < 8; k++) {
            o4[(k << 9) + t] = make_float4(r[4 * k], r[4 * k + 1],
                                           r[4 * k + 2], r[4 * k + 3]);
        }
    }
}

extern "C" void kernel_launch(void* const* d_in, const int* in_sizes, int n_in,
                              void* d_out, int out_size) {
    const float* x  = (const float*)d_in[0];
    const float* B  = (const float*)d_in[1];
    const float* G  = (const float*)d_in[2];
    const int*   Pi = (const int*)d_in[3];
    float* out = (float*)d_out;

    int rows = in_sizes[0] / L_N;

    cudaFuncSetAttribute(fwht_fused_kernel,
                         cudaFuncAttributeMaxDynamicSharedMemorySize, SMEM_BYTES);

    prep_kernel<<<L_N / 256, 256>>>(G, Pi, B);
    fwht_fused_kernel<<<rows, NT, SMEM_BYTES>>>(x, out);
}

// round 6
// speedup vs baseline: 1.3177x; 1.2008x over previous
#include <cuda_runtime.h>
#include <cuda_fp16.h>

// y = FWHT(G * Perm(FWHT(x * B))), orthonormal, L = 16384, fused one-pass.
//
// fp16 SMEM (32KB/CTA), fp32 register math. Radix-32, 512 thr/CTA, 2 CTA/SM.
// Word space q = n>>1 (u32 = half pair, n0 = half select). Bit plan per FWHT:
//   P1: fwht32 over {n0,n1,n11,n12,n13}; lanes = n2..n6 (coalesced global f4)
//   P2: fwht16 over {n2,n3,n8,n9} (n0 passenger); lanes q0,q3,q4,q5,q9
//   P3: fwht16 over {n4,n5,n6,n7} (n0 passenger); lanes q0,q1,q2,q7,q9
//   n10 = lane bit 4 in P3 -> butterfly via __shfl_xor(packed word, 16)
// Swizzle on words: b0=q0, b1=q1^q5, b2=q2^q9, b3=q3^q7, b4=q4^q2^q8 ->
// verified conflict-free for P1 (u64), P2, P3, pass5. Gather = random u16.
// Prep (every launch): Bbits sign table; Gp[Pi[n]] = G[n]/16384 (fold G+scale
// into pass-5 store); Pisw[n] = swizzled half-address of Pi[n] (u16).

#define L_N        16384
#define NQ         (L_N / 2)      // 8192 words
#define NT         512
#define SMEM_BYTES (NQ * 4)       // 32768

__device__ __align__(16) unsigned       g_Bbits[L_N / 32];
__device__ __align__(16) unsigned short g_Pisw[L_N];
__device__ __align__(16) float          g_Gp[L_N];

__device__ __forceinline__ int swq(int q) {
    int f = (((q >> 5) & 1) << 1) ^ (((q >> 9) & 1) << 2) ^ (((q >> 7) & 1) << 3)
          ^ ((((q >> 2) ^ (q >> 8)) & 1) << 4);
    return q ^ f;
}

__device__ __forceinline__ void bfly(float &a, float &b) {
    float t0 = a + b;
    float t1 = a - b;
    a = t0; b = t1;
}

__device__ __forceinline__ void fwht32(float r[32]) {
#pragma unroll
    for (int m = 1; m < 32; m <<= 1) {
#pragma unroll
        for (int i = 0; i < 32; i++) {
            if ((i & m) == 0) bfly(r[i], r[i | m]);
        }
    }
}

// 4-bit FWHT over word index (r[2*w + h], h is the n0 passenger)
__device__ __forceinline__ void fwht16x2(float r[32]) {
#pragma unroll
    for (int m = 1; m < 16; m <<= 1) {
#pragma unroll
        for (int w = 0; w < 16; w++) {
            if ((w & m) == 0) {
                bfly(r[2 * w],     r[2 * (w | m)]);
                bfly(r[2 * w + 1], r[2 * (w | m) + 1]);
            }
        }
    }
}

__device__ __forceinline__ unsigned packh2(float a, float b) {
    __half2 h = __float22half2_rn(make_float2(a, b));
    return *reinterpret_cast<unsigned*>(&h);
}
__device__ __forceinline__ float2 unpackh2(unsigned u) {
    __half2 h = *reinterpret_cast<__half2*>(&u);
    return __half22float2(h);
}

__global__ void prep_kernel(const float* __restrict__ Gv,
                            const int* __restrict__ Pi,
                            const float* __restrict__ Bv) {
    int n = blockIdx.x * blockDim.x + threadIdx.x;   // 16384 threads
    int p = Pi[n];
    g_Pisw[n] = (unsigned short)((swq(p >> 1) << 1) | (p & 1));
    g_Gp[p]   = Gv[n] * (1.0f / 16384.0f);
    unsigned sb  = __float_as_uint(Bv[n]) >> 31;
    unsigned bal = __ballot_sync(0xffffffffu, sb);
    if ((n & 31) == 0) g_Bbits[n >> 5] = bal;
}

__global__ __launch_bounds__(NT, 2)
void fwht_fused_kernel(const float* __restrict__ x,
                       float* __restrict__ out) {
    extern __shared__ unsigned s32[];   // NQ words of half2
    const int t = threadIdx.x;
    const size_t row = blockIdx.x;

    float r[32];

    // thread->word bases
    // P2: q0=t0, q3..q5=t1..t3, q9=t4, q6=t5, q10..q12=t6..t8
    const int p2q = (t & 1)
                  | (((t >> 1) & 7) << 3)
                  | (((t >> 4) & 1) << 9)
                  | (((t >> 5) & 1) << 6)
                  | (((t >> 6) & 7) << 10);
    // P3: q0..q2=t0..t2, q7=t3, q9=t4(n10 -> shfl lane bit), q8=t5, q10..q12=t6..t8
    const int p3q = (t & 7)
                  | (((t >> 3) & 1) << 7)
                  | (((t >> 4) & 1) << 9)
                  | (((t >> 5) & 1) << 8)
                  | (((t >> 6) & 7) << 10);

    // ===== FWHT#1 P1: bits {0,1,11,12,13}; coalesced f4 load; B = sign XOR =====
    {
        const float4* __restrict__ x4 = reinterpret_cast<const float4*>(x + row * L_N);
#pragma unroll
        for (int k = 0; k < 8; k++) {
            float4 xv = x4[(k << 9) + t];
            unsigned u = g_Bbits[(k << 6) + (t >> 3)] >> ((t & 7) << 2);
            r[(k << 2) + 0] = __uint_as_float(__float_as_uint(xv.x) ^ ((u & 1u) << 31));
            r[(k << 2) + 1] = __uint_as_float(__float_as_uint(xv.y) ^ ((u & 2u) << 30));
            r[(k << 2) + 2] = __uint_as_float(__float_as_uint(xv.z) ^ ((u & 4u) << 29));
            r[(k << 2) + 3] = __uint_as_float(__float_as_uint(xv.w) ^ ((u & 8u) << 28));
        }
    }
    fwht32(r);
#pragma unroll
    for (int k = 0; k < 8; k++) {
        int wq = swq((k << 10) | (t << 1));   // even; pair (wq, wq+1)
        uint2 v;
        v.x = packh2(r[(k << 2) + 0], r[(k << 2) + 1]);
        v.y = packh2(r[(k << 2) + 2], r[(k << 2) + 3]);
        *reinterpret_cast<uint2*>(&s32[wq]) = v;
    }
    __syncthreads();

    // ===== FWHT#1 P2: bits {2,3,8,9} =====
#pragma unroll
    for (int w = 0; w < 16; w++) {
        int q = p2q | ((w & 3) << 1) | ((w >> 2) << 7);
        float2 v = unpackh2(s32[swq(q)]);
        r[2 * w] = v.x; r[2 * w + 1] = v.y;
    }
    fwht16x2(r);
#pragma unroll
    for (int w = 0; w < 16; w++) {
        int q = p2q | ((w & 3) << 1) | ((w >> 2) << 7);
        s32[swq(q)] = packh2(r[2 * w], r[2 * w + 1]);
    }
    __syncthreads();

    // ===== FWHT#1 P3: load + shfl butterfly (bit 10) + bits {4,5,6,7} =====
#pragma unroll
    for (int w = 0; w < 16; w++) {
        int q = p3q | (w << 3);
        unsigned pw = s32[swq(q)];
        unsigned qw = __shfl_xor_sync(0xffffffffu, pw, 16);
        float2 a = unpackh2(pw), b = unpackh2(qw);
        if (t & 16) { r[2 * w] = b.x - a.x; r[2 * w + 1] = b.y - a.y; }
        else        { r[2 * w] = a.x + b.x; r[2 * w + 1] = a.y + b.y; }
    }
    fwht16x2(r);

    // ===== pass 5: z = y1 * Gp (G + 1/16384 folded), store =====
#pragma unroll
    for (int w = 0; w < 16; w++) {
        int q = p3q | (w << 3);
        float2 gp = *reinterpret_cast<const float2*>(&g_Gp[q << 1]);
        s32[swq(q)] = packh2(r[2 * w] * gp.x, r[2 * w + 1] * gp.y);
    }
    __syncthreads();

    // ===== gather (pre-swizzled u16 half-addresses) + shfl butterfly (bit 10) =====
    {
        const unsigned short* __restrict__ sh =
            reinterpret_cast<const unsigned short*>(s32);
#pragma unroll
        for (int w = 0; w < 16; w++) {
            int n = (p3q | (w << 3)) << 1;
            unsigned pp = *reinterpret_cast<const unsigned*>(&g_Pisw[n]);
            unsigned h0 = sh[pp & 0xffffu];
            unsigned h1 = sh[pp >> 16];
            unsigned pw = h0 | (h1 << 16);
            unsigned qw = __shfl_xor_sync(0xffffffffu, pw, 16);
            float2 a = unpackh2(pw), b = unpackh2(qw);
            if (t & 16) { r[2 * w] = b.x - a.x; r[2 * w + 1] = b.y - a.y; }
            else        { r[2 * w] = a.x + b.x; r[2 * w + 1] = a.y + b.y; }
        }
    }
    __syncthreads();   // all gathers done before smem is overwritten

    // ===== FWHT#2 P3: bits {4,5,6,7} =====
    fwht16x2(r);
#pragma unroll
    for (int w = 0; w < 16; w++) {
        int q = p3q | (w << 3);
        s32[swq(q)] = packh2(r[2 * w], r[2 * w + 1]);
    }
    __syncthreads();

    // ===== FWHT#2 P2: bits {2,3,8,9} =====
#pragma unroll
    for (int w = 0; w < 16; w++) {
        int q = p2q | ((w & 3) << 1) | ((w >> 2) << 7);
        float2 v = unpackh2(s32[swq(q)]);
        r[2 * w] = v.x; r[2 * w + 1] = v.y;
    }
    fwht16x2(r);
#pragma unroll
    for (int w = 0; w < 16; w++) {
        int q = p2q | ((w & 3) << 1) | ((w >> 2) << 7);
        s32[swq(q)] = packh2(r[2 * w], r[2 * w + 1]);
    }
    __syncthreads();

    // ===== FWHT#2 P1: bits {0,1,11,12,13}; fp32 math; coalesced f4 store =====
#pragma unroll
    for (int k = 0; k < 8; k++) {
        int wq = swq((k << 10) | (t << 1));
        uint2 v = *reinterpret_cast<const uint2*>(&s32[wq]);
        float2 ab = unpackh2(v.x), cd = unpackh2(v.y);
        r[(k << 2) + 0] = ab.x; r[(k << 2) + 1] = ab.y;
        r[(k << 2) + 2] = cd.x; r[(k << 2) + 3] = cd.y;
    }
    fwht32(r);
    {
        float4* __restrict__ o4 = reinterpret_cast<float4*>(out + row * L_N);
#pragma unroll
        for (int k = 0; k < 8; k++) {
            o4[(k << 9) + t] = make_float4(r[(k << 2) + 0], r[(k << 2) + 1],
                                           r[(k << 2) + 2], r[(k << 2) + 3]);
        }
    }
}

extern "C" void kernel_launch(void* const* d_in, const int* in_sizes, int n_in,
                              void* d_out, int out_size) {
    const float* x  = (const float*)d_in[0];
    const float* B  = (const float*)d_in[1];
    const float* G  = (const float*)d_in[2];
    const int*   Pi = (const int*)d_in[3];
    float* out = (float*)d_out;

    int rows = in_sizes[0] / L_N;

    prep_kernel<<<L_N / 256, 256>>>(G, Pi, B);
    fwht_fused_kernel<<<rows, NT, SMEM_BYTES>>>(x, out);
}

// round 7
// speedup vs baseline: 1.3352x; 1.0133x over previous
#include <cuda_runtime.h>
#include <cuda_fp16.h>

// y = FWHT(G * Perm(FWHT(x * B))), orthonormal, L = 16384, fused one-pass.
//
// fp16 SMEM (32KB/CTA), fp32 register math in PACKED f32x2 (add.rn.f32x2 /
// fma.rn.f32x2): each half2 word = value pair (n0=0, n0=1); all pair-preserving
// butterfly stages run 2 lanes/instruction. Radix-32, 512 thr/CTA, 2 CTA/SM.
// Bit plan per FWHT (word space q = n>>1):
//   P1: fwht over {n0(scalar stage),n1,n11,n12,n13}; lanes = n2..n10 (coalesced f4)
//   P2: fwht16p over word bits {q1,q2,q7,q8} = {n2,n3,n8,n9}
//   P3: fwht16p over word bits {q3..q6} = {n4..n7}; n10 via __shfl_xor(word,16)
// Swizzle swq (GF(2)-linear): b1^=q5, b2^=q9, b3^=q7, b4^=q2^q8 -> conflict-free
// for all structured passes; addresses decomposed as swq(base) ^ const[w].
// Prep (every launch): Bbits sign table; Gp[Pi[n]] = G[n]/16384 (fold G+scale
// into pass-5 store); Pisw[n] = swizzled half-address of Pi[n] (u16).

#define L_N        16384
#define NQ         (L_N / 2)
#define NT         512
#define SMEM_BYTES (NQ * 4)       // 32768

typedef unsigned long long ull;

__device__ __align__(16) unsigned       g_Bbits[L_N / 32];
__device__ __align__(16) unsigned short g_Pisw[L_N];
__device__ __align__(16) float          g_Gp[L_N];

__device__ __forceinline__ int swq(int q) {
    int f = (((q >> 5) & 1) << 1) ^ (((q >> 9) & 1) << 2) ^ (((q >> 7) & 1) << 3)
          ^ ((((q >> 2) ^ (q >> 8)) & 1) << 4);
    return q ^ f;
}

// ---- packed f32x2 helpers ----
__device__ __forceinline__ ull padd(ull a, ull b) {
    ull r; asm("add.rn.f32x2 %0, %1, %2;" : "=l"(r) : "l"(a), "l"(b)); return r;
}
__device__ __forceinline__ ull pmul(ull a, ull b) {
    ull r; asm("mul.rn.f32x2 %0, %1, %2;" : "=l"(r) : "l"(a), "l"(b)); return r;
}
__device__ __forceinline__ ull psub(ull a, ull b) {   // a - b (single rounding)
    const ull N1 = 0xBF800000BF800000ULL;             // (-1.0f, -1.0f)
    ull r; asm("fma.rn.f32x2 %0, %1, %2, %3;" : "=l"(r) : "l"(b), "l"(N1), "l"(a));
    return r;
}
__device__ __forceinline__ ull pk2(float lo, float hi) {
    ull r; asm("mov.b64 %0, {%1, %2};" : "=l"(r) : "f"(lo), "f"(hi)); return r;
}
__device__ __forceinline__ float2 upk2(ull v) {
    float2 f; asm("mov.b64 {%0, %1}, %2;" : "=f"(f.x), "=f"(f.y) : "l"(v)); return f;
}
__device__ __forceinline__ ull h2_to_p(unsigned u) {
    __half2 h = *reinterpret_cast<__half2*>(&u);
    float2 f = __half22float2(h);
    return pk2(f.x, f.y);
}
__device__ __forceinline__ unsigned p_to_h2(ull v) {
    float2 f = upk2(v);
    __half2 h = __float22half2_rn(f);
    return *reinterpret_cast<unsigned*>(&h);
}

__device__ __forceinline__ void bflyp(ull &A, ull &B) {
    ull s_ = padd(A, B);
    ull d_ = psub(A, B);
    A = s_; B = d_;
}

// packed 4-bit FWHT over word index
__device__ __forceinline__ void fwht16p(ull W[16]) {
#pragma unroll
    for (int m = 1; m < 16; m <<= 1) {
#pragma unroll
        for (int i = 0; i < 16; i++) {
            if ((i & m) == 0) bflyp(W[i], W[i | m]);
        }
    }
}

// compile-time (under unroll) swizzle deltas for phase-local word bits
__device__ __forceinline__ int d2c(int w) {   // wbits {q1,q2,q7,q8}
    int wb = ((w & 1) << 1) | (((w >> 1) & 1) << 2) | (((w >> 2) & 1) << 7)
           | (((w >> 3) & 1) << 8);
    int f = ((((w >> 1) ^ (w >> 3)) & 1) << 4) ^ (((w >> 2) & 1) << 3);
    return wb ^ f;
}
__device__ __forceinline__ int d3c(int w) {   // wbits {q3..q6}; q5 -> b1
    return (w << 3) ^ (((w >> 2) & 1) << 1);
}

__global__ void prep_kernel(const float* __restrict__ Gv,
                            const int* __restrict__ Pi,
                            const float* __restrict__ Bv) {
    int n = blockIdx.x * blockDim.x + threadIdx.x;   // 16384 threads
    int p = Pi[n];
    g_Pisw[n] = (unsigned short)((swq(p >> 1) << 1) | (p & 1));
    g_Gp[p]   = Gv[n] * (1.0f / 16384.0f);
    unsigned sb  = __float_as_uint(Bv[n]) >> 31;
    unsigned bal = __ballot_sync(0xffffffffu, sb);
    if ((n & 31) == 0) g_Bbits[n >> 5] = bal;
}

__global__ __launch_bounds__(NT, 2)
void fwht_fused_kernel(const float* __restrict__ x,
                       float* __restrict__ out) {
    extern __shared__ unsigned s32[];   // NQ half2 words
    const int t = threadIdx.x;
    const size_t row = blockIdx.x;

    ull W[16];

    // phase base words (swizzled once; phase-local bits XORed per access)
    // P1: q = (k<<10)|(t<<1)|j0 ; k bits q10..q12 have zero swizzle footprint
    const int base1 = swq(t << 1);
    // P2: q0=t0, q3..q5=t1..t3, q9=t4, q6=t5, q10..q12=t6..t8
    const int p2q = (t & 1) | (((t >> 1) & 7) << 3) | (((t >> 4) & 1) << 9)
                  | (((t >> 5) & 1) << 6) | (((t >> 6) & 7) << 10);
    const int base2 = swq(p2q);
    // P3: q0..q2=t0..t2, q7=t3, q9=t4 (n10 -> shfl), q8=t5, q10..q12=t6..t8
    const int p3q = (t & 7) | (((t >> 3) & 1) << 7) | (((t >> 4) & 1) << 9)
                  | (((t >> 5) & 1) << 8) | (((t >> 6) & 7) << 10);
    const int base3 = swq(p3q);

    // ===== FWHT#1 P1: scalar n0 stage at load, then packed {n1,n11,n12,n13} =====
    {
        const float4* __restrict__ x4 = reinterpret_cast<const float4*>(x + row * L_N);
#pragma unroll
        for (int k = 0; k < 8; k++) {
            float4 xv = x4[(k << 9) + t];
            unsigned u = g_Bbits[(k << 6) + (t >> 3)] >> ((t & 7) << 2);
            float a = __uint_as_float(__float_as_uint(xv.x) ^ ((u & 1u) << 31));
            float b = __uint_as_float(__float_as_uint(xv.y) ^ ((u & 2u) << 30));
            float c = __uint_as_float(__float_as_uint(xv.z) ^ ((u & 4u) << 29));
            float d = __uint_as_float(__float_as_uint(xv.w) ^ ((u & 8u) << 28));
            W[2 * k]     = pk2(a + b, a - b);   // word j0=0 (n1=0)
            W[2 * k + 1] = pk2(c + d, c - d);   // word j0=1 (n1=1)
        }
    }
    fwht16p(W);   // j bits: {n1, n11, n12, n13}
#pragma unroll
    for (int k = 0; k < 8; k++) {
        uint2 v;
        v.x = p_to_h2(W[2 * k]);
        v.y = p_to_h2(W[2 * k + 1]);
        *reinterpret_cast<uint2*>(&s32[base1 ^ (k << 10)]) = v;
    }
    __syncthreads();

    // ===== FWHT#1 P2: word bits {q1,q2,q7,q8} =====
#pragma unroll
    for (int w = 0; w < 16; w++) W[w] = h2_to_p(s32[base2 ^ d2c(w)]);
    fwht16p(W);
#pragma unroll
    for (int w = 0; w < 16; w++) s32[base2 ^ d2c(w)] = p_to_h2(W[w]);
    __syncthreads();

    // ===== FWHT#1 P3: shfl butterfly (n10) + word bits {q3..q6} =====
#pragma unroll
    for (int w = 0; w < 16; w++) {
        unsigned pw = s32[base3 ^ d3c(w)];
        unsigned qw = __shfl_xor_sync(0xffffffffu, pw, 16);
        ull A = h2_to_p(pw), Bp = h2_to_p(qw);
        W[w] = (t & 16) ? psub(Bp, A) : padd(A, Bp);
    }
    fwht16p(W);

    // ===== pass 5: z = y1 * Gp (G + 1/16384 folded), store =====
#pragma unroll
    for (int w = 0; w < 16; w++) {
        ull gp = *reinterpret_cast<const ull*>(&g_Gp[(p3q | (w << 3)) << 1]);
        s32[base3 ^ d3c(w)] = p_to_h2(pmul(W[w], gp));
    }
    __syncthreads();

    // ===== gather (pre-swizzled u16 half-addresses) + shfl butterfly (n10) =====
    {
        const unsigned short* __restrict__ sh =
            reinterpret_cast<const unsigned short*>(s32);
#pragma unroll
        for (int w = 0; w < 16; w++) {
            int n = (p3q | (w << 3)) << 1;
            unsigned pp = *reinterpret_cast<const unsigned*>(&g_Pisw[n]);
            unsigned h0 = sh[pp & 0xffffu];
            unsigned h1 = sh[pp >> 16];
            unsigned pw = __byte_perm(h0, h1, 0x5410);
            unsigned qw = __shfl_xor_sync(0xffffffffu, pw, 16);
            ull A = h2_to_p(pw), Bp = h2_to_p(qw);
            W[w] = (t & 16) ? psub(Bp, A) : padd(A, Bp);
        }
    }
    __syncthreads();   // all gathers done before smem is overwritten

    // ===== FWHT#2 P3: word bits {q3..q6} =====
    fwht16p(W);
#pragma unroll
    for (int w = 0; w < 16; w++) s32[base3 ^ d3c(w)] = p_to_h2(W[w]);
    __syncthreads();

    // ===== FWHT#2 P2: word bits {q1,q2,q7,q8} =====
#pragma unroll
    for (int w = 0; w < 16; w++) W[w] = h2_to_p(s32[base2 ^ d2c(w)]);
    fwht16p(W);
#pragma unroll
    for (int w = 0; w < 16; w++) s32[base2 ^ d2c(w)] = p_to_h2(W[w]);
    __syncthreads();

    // ===== FWHT#2 P1: packed {n1,n11,n12,n13}, scalar n0 stage, f4 store =====
#pragma unroll
    for (int k = 0; k < 8; k++) {
        uint2 v = *reinterpret_cast<const uint2*>(&s32[base1 ^ (k << 10)]);
        W[2 * k]     = h2_to_p(v.x);
        W[2 * k + 1] = h2_to_p(v.y);
    }
    fwht16p(W);
    {
        float4* __restrict__ o4 = reinterpret_cast<float4*>(out + row * L_N);
#pragma unroll
        for (int k = 0; k < 8; k++) {
            float2 f0 = upk2(W[2 * k]);
            float2 f1 = upk2(W[2 * k + 1]);
            o4[(k << 9) + t] = make_float4(f0.x + f0.y, f0.x - f0.y,
                                           f1.x + f1.y, f1.x - f1.y);
        }
    }
}

extern "C" void kernel_launch(void* const* d_in, const int* in_sizes, int n_in,
                              void* d_out, int out_size) {
    const float* x  = (const float*)d_in[0];
    const float* B  = (const float*)d_in[1];
    const float* G  = (const float*)d_in[2];
    const int*   Pi = (const int*)d_in[3];
    float* out = (float*)d_out;

    int rows = in_sizes[0] / L_N;

    prep_kernel<<<L_N / 256, 256>>>(G, Pi, B);
    fwht_fused_kernel<<<rows, NT, SMEM_BYTES>>>(x, out);
}